// round 17
// baseline (speedup 1.0000x reference)
#include <cuda_runtime.h>
#include <math.h>
#include <math_constants.h>
#include <stdint.h>

// Problem constants
#define BB 2
#define NN 2048
#define DIMX 768
#define HH 8
#define FF 192
#define LREL 4095            // 2*N - 1
#define QKVW 512             // H * DK

// ---------------- scratch (device globals; no allocation allowed) ----------
__device__ __align__(256) float g_pos[(size_t)LREL * FF];
__device__ __align__(256) float g_relk[(size_t)(LREL + 1) * QKVW]; // +1 pad row (stays 0)
__device__ __align__(256) float g_q[(size_t)BB * NN * QKVW];       // [b][n][h*64+d]
__device__ __align__(256) float g_k[(size_t)BB * NN * QKVW];
__device__ __align__(256) float g_v[(size_t)BB * NN * QKVW];
__device__ __align__(256) float g_o[(size_t)BB * NN * QKVW];

// ---------------- tf32 mma helpers -----------------------------------------
__device__ __forceinline__ uint32_t f2tf(float x) {
    uint32_t r; asm("cvt.rna.tf32.f32 %0, %1;" : "=r"(r) : "f"(x));
    return r;
}
__device__ __forceinline__ float tfv(float x) { return __uint_as_float(f2tf(x)); }
__device__ __forceinline__ void mma8(float* d, const uint32_t* a, const uint32_t* b) {
    asm volatile(
        "mma.sync.aligned.m16n8k8.row.col.f32.tf32.tf32.f32 "
        "{%0,%1,%2,%3},{%4,%5,%6,%7},{%8,%9},{%0,%1,%2,%3};\n"
        : "+f"(d[0]), "+f"(d[1]), "+f"(d[2]), "+f"(d[3])
        : "r"(a[0]), "r"(a[1]), "r"(a[2]), "r"(a[3]), "r"(b[0]), "r"(b[1]));
}
__device__ __forceinline__ void mma8x3(float* d, const uint32_t* ahi, const uint32_t* alo,
                                       const uint32_t* bhi, const uint32_t* blo) {
    mma8(d, ahi, blo);
    mma8(d, alo, bhi);
    mma8(d, ahi, bhi);
}
#define FU(x) __float_as_uint(x)

// ---------------- K1: positional embedding ----------------------------------
__global__ void pos_embed_kernel() {
    int row = blockIdx.x;
    int i = threadIdx.x;
    float dist = (float)(row - (NN - 1));
    float ad = fabsf(dist);

    float half_life = exp2f(3.0f + 8.0f * (float)i / 31.0f);
    float f_exp = exp2f(-ad / half_life);

    float width = exp2f((float)(i + 1)) - 1.0f;
    float f_cm = (width > ad) ? 1.0f : 0.0f;

    float mean = 64.0f * (float)(i + 1);
    float conc = (mean / 32.0f) * (mean / 32.0f);
    float rate = mean / 1024.0f;
    float log_unnorm = (conc - 1.0f) * logf(ad) - rate * ad;
    float log_norm = lgammaf(conc) - conc * logf(rate);
    float prob = expf(log_unnorm - log_norm) + 1e-8f;
    float pmax = prob;
    #pragma unroll
    for (int o = 16; o; o >>= 1) pmax = fmaxf(pmax, __shfl_xor_sync(0xFFFFFFFFu, pmax, o));
    float f_g = prob / pmax;

    float sgn = (dist > 0.0f) ? 1.0f : ((dist < 0.0f) ? -1.0f : 0.0f);

    float* out = g_pos + (size_t)row * FF;
    out[i]       = f_exp;
    out[32 + i]  = f_cm;
    out[64 + i]  = f_g;
    out[96 + i]  = sgn * f_exp;
    out[128 + i] = sgn * f_cm;
    out[160 + i] = sgn * f_g;
}

// ---------------- K2: tf32x3 GEMM v2 (unchanged) ----------------------------
#define GA 516
#define GB 260
#define VAH 0
#define VAL 4128
#define VBH 8256
#define VBL 10336
#define GEMM_SMEM ((10336 + 2080) * 4)
__global__ __launch_bounds__(256) void gemm_tf32(
    const float* __restrict__ A, const float* __restrict__ B0,
    const float* __restrict__ B1, const float* __restrict__ B2,
    const float* __restrict__ bias, float* __restrict__ C0,
    float* __restrict__ C1, float* __restrict__ C2,
    int M, int K, int Nc, int lda, int ldb, int ldc) {
    extern __shared__ float sg[];
    float* sAh = sg + VAH; float* sAl = sg + VAL;
    float* sBh = sg + VBH; float* sBl = sg + VBL;

    const float* B = B0;
    float* C = C0;
    if (blockIdx.z == 1) { B = B1; C = C1; }
    else if (blockIdx.z == 2) { B = B2; C = C2; }

    int tid = threadIdx.x;
    int warp = tid >> 5, lane = tid & 31;
    int g = lane >> 2, tig = lane & 3;
    int mw = (warp >> 1) * 32, nw = (warp & 1) * 32;
    int m0 = blockIdx.y * 128, n0 = blockIdx.x * 64;

    float acc[2][4][4] = {};

    int am = tid & 127, akg0 = tid >> 7;
    int bn = tid & 63,  bkg0 = tid >> 6;

    for (int k0 = 0; k0 < K; k0 += 32) {
        #pragma unroll
        for (int r = 0; r < 4; r++) {
            int kg = akg0 + 2 * r;
            int m = m0 + am;
            float4 v = make_float4(0.f, 0.f, 0.f, 0.f);
            if (m < M) v = *(const float4*)(A + (size_t)m * lda + k0 + kg * 4);
            float h0 = tfv(v.x), h1 = tfv(v.y), h2 = tfv(v.z), h3 = tfv(v.w);
            *(float4*)&sAh[kg * GA + am * 4] = make_float4(h0, h1, h2, h3);
            *(float4*)&sAl[kg * GA + am * 4] =
                make_float4(v.x - h0, v.y - h1, v.z - h2, v.w - h3);
        }
        #pragma unroll
        for (int r = 0; r < 2; r++) {
            int kg = bkg0 + 4 * r;
            const float* bp = B + (size_t)(k0 + kg * 4) * ldb + n0 + bn;
            float x0 = bp[0];
            float x1 = bp[(size_t)ldb];
            float x2 = bp[2 * (size_t)ldb];
            float x3 = bp[3 * (size_t)ldb];
            float h0 = tfv(x0), h1 = tfv(x1), h2 = tfv(x2), h3 = tfv(x3);
            *(float4*)&sBh[kg * GB + bn * 4] = make_float4(h0, h1, h2, h3);
            *(float4*)&sBl[kg * GB + bn * 4] =
                make_float4(x0 - h0, x1 - h1, x2 - h2, x3 - h3);
        }
        __syncthreads();
        #pragma unroll
        for (int kk = 0; kk < 32; kk += 8) {
            int qa = (kk >> 2) * GA, qb2 = (kk >> 2) * GB;
            uint32_t ah[2][4], al[2][4], bhf[4][2], blf[4][2];
            #pragma unroll
            for (int f = 0; f < 2; f++) {
                int ma = (mw + 16 * f + g) * 4 + tig;
                ah[f][0] = FU(sAh[qa + ma]);
                ah[f][1] = FU(sAh[qa + ma + 32]);
                ah[f][2] = FU(sAh[qa + GA + ma]);
                ah[f][3] = FU(sAh[qa + GA + ma + 32]);
                al[f][0] = FU(sAl[qa + ma]);
                al[f][1] = FU(sAl[qa + ma + 32]);
                al[f][2] = FU(sAl[qa + GA + ma]);
                al[f][3] = FU(sAl[qa + GA + ma + 32]);
            }
            #pragma unroll
            for (int j = 0; j < 4; j++) {
                int nb = (nw + 8 * j + g) * 4 + tig;
                bhf[j][0] = FU(sBh[qb2 + nb]);
                bhf[j][1] = FU(sBh[qb2 + GB + nb]);
                blf[j][0] = FU(sBl[qb2 + nb]);
                blf[j][1] = FU(sBl[qb2 + GB + nb]);
            }
            #pragma unroll
            for (int f = 0; f < 2; f++)
                #pragma unroll
                for (int j = 0; j < 4; j++) mma8(acc[f][j], ah[f], bhf[j]);
            #pragma unroll
            for (int f = 0; f < 2; f++)
                #pragma unroll
                for (int j = 0; j < 4; j++) mma8(acc[f][j], ah[f], blf[j]);
            #pragma unroll
            for (int f = 0; f < 2; f++)
                #pragma unroll
                for (int j = 0; j < 4; j++) mma8(acc[f][j], al[f], bhf[j]);
        }
        __syncthreads();
    }

    #pragma unroll
    for (int f = 0; f < 2; f++) {
        #pragma unroll
        for (int j = 0; j < 4; j++) {
            int n = n0 + nw + 8 * j + 2 * tig;
            float b0v = bias ? bias[n] : 0.0f;
            float b1v = bias ? bias[n + 1] : 0.0f;
            int m = m0 + mw + 16 * f + g;
            if (m < M)
                *(float2*)(C + (size_t)m * ldc + n) =
                    make_float2(acc[f][j][0] + b0v, acc[f][j][1] + b1v);
            if (m + 8 < M)
                *(float2*)(C + (size_t)(m + 8) * ldc + n) =
                    make_float2(acc[f][j][2] + b0v, acc[f][j][3] + b1v);
        }
    }
}

// ---------------- K3: fused attention v5 — raw tiles, 103KB smem, 2 CTA/SM --
// K/band/V/P in plain k4 B-layout: elem(k,n) at (k>>2)*260 + 4n + (k&3).
// Q-lo in k4 A-layout. hi/lo split for K/band done at fragment-load time.
// P region ALIASES the K buffer (K dead after content mma; 2 barriers apart).
#define FRK 0                      // K raw 16*260=4160; P-hi after S4
#define FRB 4160                   // band raw 4160
#define FQL 8320                   // Q-lo 4160
#define FVS 12480                  // V 4160
#define FGB 16640                  // G buf 2 x 4352 (slot0 = Q temp in prologue)
#define FCB 25344                  // cb[64]
#define FDB 25408                  // db[2][64]
#define FREDM 25536                // 128
#define FREDS 25664                // 128
#define FSM_TOT 25792              // *4 = 103,168 B  (2 CTAs/SM)
#define GSLOT2 4352

// raw-load 64x64 tile (row-major, ld=QKVW) into k4 B-layout (no split)
__device__ __forceinline__ void ld_raw(const float* src, float* dst, int tid) {
    int n = tid & 63, dg = tid >> 6;
    #pragma unroll
    for (int r = 0; r < 4; r++) {
        int grp = dg + 4 * r;
        float4 v = *(const float4*)(src + (size_t)n * QKVW + grp * 4);
        *(float4*)&dst[grp * 260 + 4 * n] = v;
    }
}
// V loader: k4 B-operand layout (k = seq row, n = dv), rna-rounded
__device__ __forceinline__ void ld_v(const float* src, float* dv, int tid) {
    int row = tid & 63, dg = tid >> 6;
    #pragma unroll
    for (int r = 0; r < 4; r++) {
        int grp = dg + 4 * r;
        float4 v = *(const float4*)(src + (size_t)row * QKVW + grp * 4);
        int bb = (row >> 2) * 260 + (row & 3);
        dv[bb + (grp * 4 + 0) * 4] = tfv(v.x);
        dv[bb + (grp * 4 + 1) * 4] = tfv(v.y);
        dv[bb + (grp * 4 + 2) * 4] = tfv(v.z);
        dv[bb + (grp * 4 + 3) * 4] = tfv(v.w);
    }
}

__global__ __launch_bounds__(256, 2) void attn_fused(const float* __restrict__ rcb,
                                                     const float* __restrict__ rpb) {
    extern __shared__ float sm[];

    int bhid = blockIdx.y;
    int b = bhid >> 3, h = bhid & 7;
    int i0 = blockIdx.x * 64;
    int tid = threadIdx.x, warp = tid >> 5, lane = tid & 31;
    int g = lane >> 2, tig = lane & 3;
    int mwl = (warp >> 1) * 16, nwl = (warp & 1) * 32;
    int li0 = mwl + g, li1 = li0 + 8;

    const float* qb = g_q + (size_t)b * NN * QKVW + h * 64;
    const float* kb = g_k + (size_t)b * NN * QKVW + h * 64;
    const float* vb = g_v + (size_t)b * NN * QKVW + h * 64;
    int relbase = 1984 - i0;

    // ---- prologue: Qraw (scaled) -> FGB slot0 temp; band chunk0 -> FRB ----
    {
        int row = tid & 63, dg = tid >> 6;
        #pragma unroll
        for (int r = 0; r < 4; r++) {
            int grp = dg + 4 * r;
            float4 v = *(const float4*)(qb + (size_t)(i0 + row) * QKVW + grp * 4);
            *(float4*)&sm[FGB + row * 68 + grp * 4] =
                make_float4(v.x * 0.125f, v.y * 0.125f, v.z * 0.125f, v.w * 0.125f);
        }
    }
    ld_raw(g_relk + (size_t)relbase * QKVW + h * 64, sm + FRB, tid);
    __syncthreads();   // P1

    // extract Q hi to regs; lower-n warps write Q lo to FQL (dup rows benign-free)
    uint32_t qh[8][4];
    #pragma unroll
    for (int kkg = 0; kkg < 8; kkg++) {
        int kk = 8 * kkg;
        float a0 = sm[FGB + li0 * 68 + kk + tig];
        float a1 = sm[FGB + li1 * 68 + kk + tig];
        float a2 = sm[FGB + li0 * 68 + kk + tig + 4];
        float a3 = sm[FGB + li1 * 68 + kk + tig + 4];
        float h0 = tfv(a0), h1 = tfv(a1), h2 = tfv(a2), h3 = tfv(a3);
        qh[kkg][0] = FU(h0); qh[kkg][1] = FU(h1); qh[kkg][2] = FU(h2); qh[kkg][3] = FU(h3);
        if (nwl == 0) {
            sm[FQL + 2 * kkg * 260 + 4 * li0 + tig]       = a0 - h0;
            sm[FQL + 2 * kkg * 260 + 4 * li1 + tig]       = a1 - h1;
            sm[FQL + (2 * kkg + 1) * 260 + 4 * li0 + tig] = a2 - h2;
            sm[FQL + (2 * kkg + 1) * 260 + 4 * li1 + tig] = a3 - h3;
        }
    }

    // db[0] from band chunk0 (raw reads)
    {
        int col = tid >> 2;
        float accd = 0.0f;
        #pragma unroll
        for (int dd = 0; dd < 16; dd++) {
            int d = (tid & 3) + 4 * dd;
            float bv = sm[FRB + dd * 260 + 4 * col + (tid & 3)];
            accd = fmaf(rpb[h * 64 + d], bv, accd);
        }
        accd += __shfl_xor_sync(0xFFFFFFFFu, accd, 1);
        accd += __shfl_xor_sync(0xFFFFFFFFu, accd, 2);
        if ((tid & 3) == 0) sm[FDB + col] = accd;
    }
    __syncthreads();   // P2: FQL + db0 visible; FGB(Q temp) free

    // G chunk0 -> Gbuf slot 0
    {
        float gacc[4][4] = {};
        #pragma unroll
        for (int kkg = 0; kkg < 8; kkg++) {
            uint32_t al[4];
            al[0] = FU(sm[FQL + 2 * kkg * 260 + 4 * li0 + tig]);
            al[1] = FU(sm[FQL + 2 * kkg * 260 + 4 * li1 + tig]);
            al[2] = FU(sm[FQL + (2 * kkg + 1) * 260 + 4 * li0 + tig]);
            al[3] = FU(sm[FQL + (2 * kkg + 1) * 260 + 4 * li1 + tig]);
            #pragma unroll
            for (int j = 0; j < 4; j++) {
                int nb = 4 * (nwl + 8 * j + g) + tig;
                float x0 = sm[FRB + 2 * kkg * 260 + nb];
                float x1 = sm[FRB + (2 * kkg + 1) * 260 + nb];
                float h0 = tfv(x0), h1 = tfv(x1);
                uint32_t bh2[2] = { FU(h0), FU(h1) };
                uint32_t bl2[2] = { FU(x0 - h0), FU(x1 - h1) };
                mma8x3(gacc[j], qh[kkg], al, bh2, bl2);
            }
        }
        float* Gb = sm + FGB;
        #pragma unroll
        for (int j = 0; j < 4; j++) {
            int c = nwl + 8 * j + 2 * tig;
            *(float2*)&Gb[li0 * 68 + c] = make_float2(gacc[j][0], gacc[j][1]);
            *(float2*)&Gb[li1 * 68 + c] = make_float2(gacc[j][2], gacc[j][3]);
        }
    }

    float oacc[4][4] = {};
    float m0r = -CUDART_INF_F, m1r = -CUDART_INF_F;
    float l0 = 0.0f, l1 = 0.0f;

    for (int t = 0; t < 32; t++) {
        __syncthreads();   // S1
        ld_raw(kb + (size_t)t * 64 * QKVW, sm + FRK, tid);
        ld_v(vb + (size_t)t * 64 * QKVW, sm + FVS, tid);
        ld_raw(g_relk + (size_t)(relbase + 64 * (t + 1)) * QKVW + h * 64,
               sm + FRB, tid);
        __syncthreads();   // S2

        // cb (from K) and db[(t+1)&1] (from band) — raw reads
        {
            int col = tid >> 2;
            float accc = 0.0f, accd = 0.0f;
            #pragma unroll
            for (int dd = 0; dd < 16; dd++) {
                int d = (tid & 3) + 4 * dd;
                int off = dd * 260 + 4 * col + (tid & 3);
                float kv = sm[FRK + off];
                float bv = sm[FRB + off];
                accc = fmaf(rcb[h * 64 + d], kv, accc);
                accd = fmaf(rpb[h * 64 + d], bv, accd);
            }
            accc += __shfl_xor_sync(0xFFFFFFFFu, accc, 1);
            accc += __shfl_xor_sync(0xFFFFFFFFu, accc, 2);
            accd += __shfl_xor_sync(0xFFFFFFFFu, accd, 1);
            accd += __shfl_xor_sync(0xFFFFFFFFu, accd, 2);
            if ((tid & 3) == 0) {
                sm[FCB + col] = accc;
                sm[FDB + ((t + 1) & 1) * 64 + col] = accd;
            }
        }

        // content mma: cacc = Q x K (split K at fragment load)
        float cacc[4][4] = {};
        #pragma unroll
        for (int kkg = 0; kkg < 8; kkg++) {
            uint32_t al[4];
            al[0] = FU(sm[FQL + 2 * kkg * 260 + 4 * li0 + tig]);
            al[1] = FU(sm[FQL + 2 * kkg * 260 + 4 * li1 + tig]);
            al[2] = FU(sm[FQL + (2 * kkg + 1) * 260 + 4 * li0 + tig]);
            al[3] = FU(sm[FQL + (2 * kkg + 1) * 260 + 4 * li1 + tig]);
            #pragma unroll
            for (int j = 0; j < 4; j++) {
                int nb = 4 * (nwl + 8 * j + g) + tig;
                float x0 = sm[FRK + 2 * kkg * 260 + nb];
                float x1 = sm[FRK + (2 * kkg + 1) * 260 + nb];
                float h0 = tfv(x0), h1 = tfv(x1);
                uint32_t bh2[2] = { FU(h0), FU(h1) };
                uint32_t bl2[2] = { FU(x0 - h0), FU(x1 - h1) };
                mma8x3(cacc[j], qh[kkg], al, bh2, bl2);
            }
        }

        // G mma chunk t+1 -> Gbuf slot (t+1)&1
        {
            float gacc[4][4] = {};
            #pragma unroll
            for (int kkg = 0; kkg < 8; kkg++) {
                uint32_t al[4];
                al[0] = FU(sm[FQL + 2 * kkg * 260 + 4 * li0 + tig]);
                al[1] = FU(sm[FQL + 2 * kkg * 260 + 4 * li1 + tig]);
                al[2] = FU(sm[FQL + (2 * kkg + 1) * 260 + 4 * li0 + tig]);
                al[3] = FU(sm[FQL + (2 * kkg + 1) * 260 + 4 * li1 + tig]);
                #pragma unroll
                for (int j = 0; j < 4; j++) {
                    int nb = 4 * (nwl + 8 * j + g) + tig;
                    float x0 = sm[FRB + 2 * kkg * 260 + nb];
                    float x1 = sm[FRB + (2 * kkg + 1) * 260 + nb];
                    float h0 = tfv(x0), h1 = tfv(x1);
                    uint32_t bh2[2] = { FU(h0), FU(h1) };
                    uint32_t bl2[2] = { FU(x0 - h0), FU(x1 - h1) };
                    mma8x3(gacc[j], qh[kkg], al, bh2, bl2);
                }
            }
            float* Gb = sm + FGB + ((t + 1) & 1) * GSLOT2;
            #pragma unroll
            for (int j = 0; j < 4; j++) {
                int c = nwl + 8 * j + 2 * tig;
                *(float2*)&Gb[li0 * 68 + c] = make_float2(gacc[j][0], gacc[j][1]);
                *(float2*)&Gb[li1 * 68 + c] = make_float2(gacc[j][2], gacc[j][3]);
            }
        }
        __syncthreads();   // S3

        // gather + biases + rowmax
        const float* G0 = sm + FGB + (t & 1) * GSLOT2;
        const float* G1 = sm + FGB + ((t + 1) & 1) * GSLOT2;
        const float* db0 = sm + FDB + (t & 1) * 64;
        const float* db1 = sm + FDB + ((t + 1) & 1) * 64;
        float s0[8], s1[8];
        float rm0 = -CUDART_INF_F, rm1 = -CUDART_INF_F;
        #pragma unroll
        for (int j = 0; j < 4; j++) {
            #pragma unroll
            for (int e = 0; e < 2; e++) {
                int lj = nwl + 8 * j + 2 * tig + e;
                float cbv = sm[FCB + lj];
                int rl0 = lj - li0 + 63;
                int rl1 = lj - li1 + 63;
                float gv0 = (rl0 < 64) ? (G0[li0 * 68 + rl0] + db0[rl0])
                                       : (G1[li0 * 68 + rl0 - 64] + db1[rl0 - 64]);
                float gv1 = (rl1 < 64) ? (G0[li1 * 68 + rl1] + db0[rl1])
                                       : (G1[li1 * 68 + rl1 - 64] + db1[rl1 - 64]);
                float v0 = cacc[j][e]     + gv0 + cbv;
                float v1 = cacc[j][2 + e] + gv1 + cbv;
                s0[2 * j + e] = v0; s1[2 * j + e] = v1;
                rm0 = fmaxf(rm0, v0); rm1 = fmaxf(rm1, v1);
            }
        }
        rm0 = fmaxf(rm0, __shfl_xor_sync(0xFFFFFFFFu, rm0, 1));
        rm0 = fmaxf(rm0, __shfl_xor_sync(0xFFFFFFFFu, rm0, 2));
        rm1 = fmaxf(rm1, __shfl_xor_sync(0xFFFFFFFFu, rm1, 1));
        rm1 = fmaxf(rm1, __shfl_xor_sync(0xFFFFFFFFu, rm1, 2));
        if (tig == 0) {
            sm[FREDM + (warp & 1) * 64 + li0] = rm0;
            sm[FREDM + (warp & 1) * 64 + li1] = rm1;
        }
        __syncthreads();   // S4

        float mn0 = fmaxf(m0r, fmaxf(sm[FREDM + li0], sm[FREDM + 64 + li0]));
        float mn1 = fmaxf(m1r, fmaxf(sm[FREDM + li1], sm[FREDM + 64 + li1]));
        float sc0 = __expf(m0r - mn0), sc1 = __expf(m1r - mn1);
        m0r = mn0; m1r = mn1;
        float rs0 = 0.0f, rs1 = 0.0f;
        #pragma unroll
        for (int j = 0; j < 4; j++) {
            oacc[j][0] *= sc0; oacc[j][1] *= sc0;
            oacc[j][2] *= sc1; oacc[j][3] *= sc1;
            float p0a = __expf(s0[2 * j] - mn0), p0b = __expf(s0[2 * j + 1] - mn0);
            float p1a = __expf(s1[2 * j] - mn1), p1b = __expf(s1[2 * j + 1] - mn1);
            rs0 += p0a + p0b; rs1 += p1a + p1b;
            // P hi -> FRK region (K dead; 2 barriers since last K read)
            int c = nwl + 8 * j + 2 * tig;
            int pb = FRK + (c >> 2) * 260 + (c & 3);
            *(float2*)&sm[pb + 4 * li0] = make_float2(tfv(p0a), tfv(p0b));
            *(float2*)&sm[pb + 4 * li1] = make_float2(tfv(p1a), tfv(p1b));
        }
        rs0 += __shfl_xor_sync(0xFFFFFFFFu, rs0, 1);
        rs0 += __shfl_xor_sync(0xFFFFFFFFu, rs0, 2);
        rs1 += __shfl_xor_sync(0xFFFFFFFFu, rs1, 1);
        rs1 += __shfl_xor_sync(0xFFFFFFFFu, rs1, 2);
        if (tig == 0) {
            sm[FREDS + (warp & 1) * 64 + li0] = rs0;
            sm[FREDS + (warp & 1) * 64 + li1] = rs1;
        }
        __syncthreads();   // S5

        l0 = l0 * sc0 + sm[FREDS + li0] + sm[FREDS + 64 + li0];
        l1 = l1 * sc1 + sm[FREDS + li1] + sm[FREDS + 64 + li1];

        // PV mma: oacc += P x V  (P hi-only in FRK, V rna)
        #pragma unroll
        for (int kkg = 0; kkg < 8; kkg++) {
            uint32_t ph[4];
            ph[0] = FU(sm[FRK + 2 * kkg * 260 + 4 * li0 + tig]);
            ph[1] = FU(sm[FRK + 2 * kkg * 260 + 4 * li1 + tig]);
            ph[2] = FU(sm[FRK + (2 * kkg + 1) * 260 + 4 * li0 + tig]);
            ph[3] = FU(sm[FRK + (2 * kkg + 1) * 260 + 4 * li1 + tig]);
            #pragma unroll
            for (int j = 0; j < 4; j++) {
                int n = nwl + 8 * j + g;
                uint32_t bf[2] = { FU(sm[FVS + 2 * kkg * 260 + 4 * n + tig]),
                                   FU(sm[FVS + (2 * kkg + 1) * 260 + 4 * n + tig]) };
                mma8(oacc[j], ph, bf);
            }
        }
    }

    float inv0 = 1.0f / l0, inv1 = 1.0f / l1;
    float* ob = g_o + (size_t)(b * NN + i0) * QKVW + h * 64;
    #pragma unroll
    for (int j = 0; j < 4; j++) {
        int c = nwl + 8 * j + 2 * tig;
        *(float2*)(ob + (size_t)li0 * QKVW + c) =
            make_float2(oacc[j][0] * inv0, oacc[j][1] * inv0);
        *(float2*)(ob + (size_t)li1 * QKVW + c) =
            make_float2(oacc[j][2] * inv1, oacc[j][3] * inv1);
    }
}

// ---------------- launch ----------------------------------------------------
static float* sym_addr(const void* sym) {
    void* p = nullptr;
    cudaGetSymbolAddress(&p, sym);
    return (float*)p;
}

extern "C" void kernel_launch(void* const* d_in, const int* in_sizes, int n_in,
                              void* d_out, int out_size) {
    const float* x    = (const float*)d_in[0];
    const float* Wq   = (const float*)d_in[1];
    const float* Wk   = (const float*)d_in[2];
    const float* Wv   = (const float*)d_in[3];
    const float* Wrel = (const float*)d_in[4];
    const float* Wout = (const float*)d_in[5];
    const float* bout = (const float*)d_in[6];
    const float* rcb  = (const float*)d_in[7];
    const float* rpb  = (const float*)d_in[8];
    float* out = (float*)d_out;

    float* p_pos  = sym_addr(g_pos);
    float* p_relk = sym_addr(g_relk);
    float* p_q    = sym_addr(g_q);
    float* p_k    = sym_addr(g_k);
    float* p_v    = sym_addr(g_v);
    float* p_o    = sym_addr(g_o);

    cudaFuncSetAttribute(gemm_tf32, cudaFuncAttributeMaxDynamicSharedMemorySize,
                         GEMM_SMEM);
    const int FUSED_SMEM = FSM_TOT * 4;   // 103,168 B -> 2 CTAs/SM
    cudaFuncSetAttribute(attn_fused, cudaFuncAttributeMaxDynamicSharedMemorySize,
                         FUSED_SMEM);

    // 1. positional embedding
    pos_embed_kernel<<<LREL, 32>>>();

    // 2. rel_k = pos @ Wrel  (row 4095 of g_relk stays 0 = pad)
    gemm_tf32<<<dim3(QKVW / 64, 32, 1), 256, GEMM_SMEM>>>(
        p_pos, Wrel, nullptr, nullptr, nullptr, p_relk, nullptr, nullptr,
        LREL, FF, QKVW, FF, QKVW, QKVW);

    // 3. q,k,v projections fused into one launch
    gemm_tf32<<<dim3(QKVW / 64, (BB * NN) / 128, 3), 256, GEMM_SMEM>>>(
        x, Wq, Wk, Wv, nullptr, p_q, p_k, p_v,
        BB * NN, DIMX, QKVW, DIMX, QKVW, QKVW);

    // 4. fused logits + online softmax + P@V  (256 threads, 2 CTAs/SM)
    attn_fused<<<dim3(NN / 64, BB * HH), 256, FUSED_SMEM>>>(rcb, rpb);

    // 5. out = O @ Wout + b_out
    gemm_tf32<<<dim3(DIMX / 64, (BB * NN) / 128, 1), 256, GEMM_SMEM>>>(
        p_o, Wout, nullptr, nullptr, bout, out, nullptr, nullptr,
        BB * NN, QKVW, DIMX, QKVW, DIMX, DIMX);
}